// round 7
// baseline (speedup 1.0000x reference)
#include <cuda_runtime.h>
#include <cstddef>
#include <math_constants.h>

#define NNODES 4096
#define NB 4
#define BN (NNODES * NB)
#define DFEAT 240
#define KNN 8
#define NCHUNK 2
#define CHUNK (NNODES / NCHUNK)   // 2048 candidates per chunk

// Scratch (allocation-free rule: __device__ globals)
__device__ int   g_knn[BN * KNN];
__device__ float g_pd[BN * NCHUNK * KNN];
__device__ int   g_pi[BN * NCHUNK * KNN];
// Fused (W @ L) matrices, output scales baked in
__device__ float g_WL0[32 * 64];   // (W2@L0)  * c2/8
__device__ float g_WL1a[64 * 32];  // (W1@L1)  * c1/sqrt(32)
__device__ float g_WL1b[16 * 32];  // (W4@L1)  * c4/sqrt(32)
__device__ float g_WL2[32 * 16];   // (W3@L2)  * c3/4

// T[a][k] = (Cm[a] . ev)[k], Cm = real Wigner 1x1->2 coupling / sqrt(5)
__device__ __forceinline__ void compute_T(float ex, float ey, float ez, float T[5][3]) {
    const float sc = 0.31622776601683794f;   // 1/sqrt(2)/sqrt(5)
    const float tc = 0.18257418583505536f;   // 1/sqrt(6)/sqrt(5)
    T[0][0] = sc * ey;  T[0][1] = sc * ex;   T[0][2] = 0.f;
    T[1][0] = sc * ez;  T[1][1] = 0.f;       T[1][2] = sc * ex;
    T[2][0] = 0.f;      T[2][1] = sc * ez;   T[2][2] = sc * ey;
    T[3][0] = sc * ex;  T[3][1] = -sc * ey;  T[3][2] = 0.f;
    T[4][0] = -tc * ex; T[4][1] = -tc * ey;  T[4][2] = 2.f * tc * ez;
}

// Branchless sorted insert (ascending; bd[7] = worst). Compare-exchange sweep.
// NO-OP when s >= bd[7] (pred false at every level) -> safe to call
// unconditionally. Ties: strict < keeps earlier-inserted (smaller index) ahead.
__device__ __forceinline__ void bubble_insert(float bd[8], int bi[8], float s, int gj) {
    float cur = s; int curi = gj;
#pragma unroll
    for (int p = 0; p < 8; p++) {
        bool pred = cur < bd[p];
        float lo = fminf(bd[p], cur);
        float hi = fmaxf(bd[p], cur);
        bd[p] = lo; cur = hi;
        int ti = bi[p];
        bi[p] = pred ? curi : bi[p];
        curi  = pred ? ti   : curi;
    }
}

// ============================================================================
// Kernel 1a: partial kNN. Thread = (query, half). Scans 2048 candidates from
// a float4 (x,y,z,|c|^2/2) shared tile; rank by s = h - q.c (monotone in d^2).
// ONE branch per 4-candidate group (min4 pretest); inside, all 4 inserts are
// unconditional (no-op-safe) -> no inner BSSY/BSYNC divergence overhead.
// Self-exclusion folded into the data path via SEL to +inf.
// ============================================================================
__global__ __launch_bounds__(128) void knn_part_kernel(const float* __restrict__ coords) {
    __shared__ float4 tile[CHUNK];                // 32KB
    int b = blockIdx.y, chunk = blockIdx.z;
    int cbase = chunk * CHUNK;
    const float* cb = coords + (size_t)b * NNODES * 3;

    for (int k = threadIdx.x; k < CHUNK; k += 128) {
        float x = cb[(cbase + k) * 3];
        float y = cb[(cbase + k) * 3 + 1];
        float z = cb[(cbase + k) * 3 + 2];
        tile[k] = make_float4(x, y, z, 0.5f * fmaf(x, x, fmaf(y, y, z * z)));
    }
    __syncthreads();

    int q = (blockIdx.x << 7) + threadIdx.x;
    float qx = cb[3 * q], qy = cb[3 * q + 1], qz = cb[3 * q + 2];
    float nqx = -qx, nqy = -qy, nqz = -qz;
    int qrel = q - cbase;                         // self index within chunk (may be out of range)

    float bd[8];
    int   bi[8];
#pragma unroll
    for (int p = 0; p < 8; p++) { bd[p] = 3.9e38f; bi[p] = 0x7fffffff; }

#pragma unroll 2
    for (int g = 0; g < CHUNK; g += 4) {
        float4 c0 = tile[g],     c1 = tile[g + 1];
        float4 c2 = tile[g + 2], c3 = tile[g + 3];
        float s0 = fmaf(nqx, c0.x, fmaf(nqy, c0.y, fmaf(nqz, c0.z, c0.w)));
        float s1 = fmaf(nqx, c1.x, fmaf(nqy, c1.y, fmaf(nqz, c1.z, c1.w)));
        float s2 = fmaf(nqx, c2.x, fmaf(nqy, c2.y, fmaf(nqz, c2.z, c2.w)));
        float s3 = fmaf(nqx, c3.x, fmaf(nqy, c3.y, fmaf(nqz, c3.z, c3.w)));
        // self-exclusion on the data path (2 instr/cand, no branch)
        s0 = (g     == qrel) ? CUDART_INF_F : s0;
        s1 = (g + 1 == qrel) ? CUDART_INF_F : s1;
        s2 = (g + 2 == qrel) ? CUDART_INF_F : s2;
        s3 = (g + 3 == qrel) ? CUDART_INF_F : s3;
        float m = fminf(fminf(s0, s1), fminf(s2, s3));
        if (m < bd[7]) {                          // single divergent branch per group
            int j0 = cbase + g;
            bubble_insert(bd, bi, s0, j0);        // unconditional: no-op if s >= worst
            bubble_insert(bd, bi, s1, j0 + 1);
            bubble_insert(bd, bi, s2, j0 + 2);
            bubble_insert(bd, bi, s3, j0 + 3);
        }
    }

    int qflat = b * NNODES + q;
    int obase = (qflat * NCHUNK + chunk) * KNN;
#pragma unroll
    for (int r = 0; r < KNN; r++) {
        g_pd[obase + r] = bd[r];
        g_pi[obase + r] = b * NNODES + bi[r];     // flat sender id
    }
}

// ============================================================================
// Kernel 1b: merge. Warp per query: 16 partials in lanes 0-15, 8 rounds of
// lexicographic (val, idx) butterfly argmin; winner masked out by unique id.
// ============================================================================
__global__ __launch_bounds__(256) void knn_merge_kernel() {
    int warp = threadIdx.x >> 5, lane = threadIdx.x & 31;
    int qf = blockIdx.x * 8 + warp;
    int base = qf * NCHUNK * KNN;                 // 16 contiguous entries

    float v = (lane < 16) ? g_pd[base + lane] : 3.95e38f;
    int  id = (lane < 16) ? g_pi[base + lane] : 0x7fffffff;

#pragma unroll
    for (int r = 0; r < KNN; r++) {
        float mv = v; int mi = id;
#pragma unroll
        for (int off = 16; off >= 1; off >>= 1) {
            float ov = __shfl_xor_sync(0xffffffffu, mv, off);
            int   oi = __shfl_xor_sync(0xffffffffu, mi, off);
            if (ov < mv || (ov == mv && oi < mi)) { mv = ov; mi = oi; }
        }
        if (lane == r) g_knn[qf * KNN + r] = mi;  // spread stores
        if (id == mi) v = 3.95e38f;               // node ids unique across chunks
    }
}

// ============================================================================
// Kernel 2: fuse W and L matrices (W commutes with aggregation) + bake scales.
// ============================================================================
__global__ __launch_bounds__(256) void fuse_kernel(
    const float* __restrict__ W1, const float* __restrict__ W2,
    const float* __restrict__ W3, const float* __restrict__ W4,
    const float* __restrict__ L0, const float* __restrict__ L1,
    const float* __restrict__ L2) {
    const float c1 = 0.11180339887498949f;   // sqrt(1/80)
    const float c2 = 0.10206207261596575f;   // sqrt(1/96)
    const float c3 = 0.39528470752104744f;   // sqrt(5/32)
    const float c4 = 0.19364916731037085f;   // sqrt(3/80)
    const float is32 = 0.17677669529663687f; // 1/sqrt(32)
    int idx = blockIdx.x * 256 + threadIdx.x;
    if (idx < 2048) {                         // WL0 = W2@L0 : (32,64)
        int u = idx >> 6, w2 = idx & 63;
        float acc = 0.f;
        for (int w = 0; w < 64; w++) acc = fmaf(W2[u * 64 + w], L0[w * 64 + w2], acc);
        g_WL0[idx] = (c2 * 0.125f) * acc;
    } else if (idx < 4096) {                  // WL1a = W1@L1 : (64,32)
        int t = idx - 2048, u = t >> 5, w2 = t & 31;
        float acc = 0.f;
        for (int w = 0; w < 32; w++) acc = fmaf(W1[u * 32 + w], L1[w * 32 + w2], acc);
        g_WL1a[t] = (c1 * is32) * acc;
    } else if (idx < 4608) {                  // WL1b = W4@L1 : (16,32)
        int t = idx - 4096, u = t >> 5, w2 = t & 31;
        float acc = 0.f;
        for (int w = 0; w < 32; w++) acc = fmaf(W4[u * 32 + w], L1[w * 32 + w2], acc);
        g_WL1b[t] = (c4 * is32) * acc;
    } else {                                  // WL2 = W3@L2 : (32,16)
        int t = idx - 4608, u = t >> 4, w2 = t & 15;
        float acc = 0.f;
        for (int w = 0; w < 16; w++) acc = fmaf(W3[u * 16 + w], L2[w * 16 + w2], acc);
        g_WL2[t] = (c3 * 0.25f) * acc;
    }
}

// ============================================================================
// Kernel 3: fused aggregation. Warp per node. Direct LDG of exactly the
// feature elements each lane needs; neighbor ids + coords front-batched.
// Then fused WL linears from shared.
// ============================================================================
__global__ __launch_bounds__(256) void agg_kernel(
    const float* __restrict__ feats, const float* __restrict__ coords,
    float* __restrict__ out) {
    __shared__ float sWL0[2048], sWL1a[2048], sWL1b[512], sWL2[512];
    __shared__ float sag[8][440];
    for (int k = threadIdx.x; k < 2048; k += 256) { sWL0[k] = g_WL0[k]; sWL1a[k] = g_WL1a[k]; }
    for (int k = threadIdx.x; k < 512;  k += 256) { sWL1b[k] = g_WL1b[k]; sWL2[k] = g_WL2[k]; }

    int warp = threadIdx.x >> 5, lane = threadIdx.x & 31;
    int node = (blockIdx.x << 3) + warp;
    float qx = coords[node * 3], qy = coords[node * 3 + 1], qz = coords[node * 3 + 2];

    // front-batch neighbor ids (32B aligned) and edge vectors
    int4 n0 = *(const int4*)(g_knn + node * KNN);
    int4 n1 = *(const int4*)(g_knn + node * KNN + 4);
    int nbr[8] = {n0.x, n0.y, n0.z, n0.w, n1.x, n1.y, n1.z, n1.w};
    float ex[8], ey[8], ez[8];
#pragma unroll
    for (int r = 0; r < 8; r++) {
        ex[r] = coords[nbr[r] * 3]     - qx;
        ey[r] = coords[nbr[r] * 3 + 1] - qy;
        ez[r] = coords[nbr[r] * 3 + 2] - qz;
    }

    float a0 = 0.f;
    float a1a0[3] = {0.f, 0.f, 0.f};
    float a1a1[3] = {0.f, 0.f, 0.f};
    float a1b[3]  = {0.f, 0.f, 0.f};
    float a2[5]   = {0.f, 0.f, 0.f, 0.f, 0.f};

#pragma unroll
    for (int r = 0; r < KNN; r++) {
        const float* f = feats + (size_t)nbr[r] * DFEAT;
        float f0a = f[lane];                       // coalesced
        float f0b = f[32 + lane];                  // coalesced
        float x1v[3];
#pragma unroll
        for (int i = 0; i < 3; i++) x1v[i] = f[64 + 3 * lane + i];
        float x2v[5];
        if (lane < 16) {
#pragma unroll
            for (int a = 0; a < 5; a++) x2v[a] = f[160 + 5 * lane + a];
        }

        float T[5][3];
        compute_T(ex[r], ey[r], ez[r], T);
        float e[3] = {ex[r], ey[r], ez[r]};

#pragma unroll
        for (int k = 0; k < 3; k++) {
            a1a0[k] = fmaf(f0a, e[k], a1a0[k]);
            a1a1[k] = fmaf(f0b, e[k], a1a1[k]);
        }
#pragma unroll
        for (int i = 0; i < 3; i++) a0 = fmaf(x1v[i], e[i], a0);
#pragma unroll
        for (int a = 0; a < 5; a++)
#pragma unroll
            for (int i = 0; i < 3; i++) a2[a] = fmaf(x1v[i], T[a][i], a2[a]);
        if (lane < 16) {
#pragma unroll
            for (int a = 0; a < 5; a++)
#pragma unroll
                for (int k = 0; k < 3; k++) a1b[k] = fmaf(x2v[a], T[a][k], a1b[k]);
        }
    }

    __syncthreads();   // sWL ready

    // stage aggregates: [0,32) a0 | 32+3u+k (u<64) a1a | 224+3u+k (u<16) a1b | 272+5u+a a2
    float* ag = sag[warp];
    ag[lane] = a0;
#pragma unroll
    for (int k = 0; k < 3; k++) {
        ag[32 + 3 * lane + k]        = a1a0[k];
        ag[32 + 3 * (lane + 32) + k] = a1a1[k];
    }
    if (lane < 16) {
#pragma unroll
        for (int k = 0; k < 3; k++) ag[224 + 3 * lane + k] = a1b[k];
    }
#pragma unroll
    for (int a = 0; a < 5; a++) ag[272 + 5 * lane + a] = a2[a];
    __syncwarp();

    float* o = out + (size_t)node * DFEAT;
    {   // y0[w'] = sum_u a0[u] WL0[u,w']   (w' = 2lane, 2lane+1)
        float y0 = 0.f, y1v = 0.f;
#pragma unroll
        for (int u = 0; u < 32; u++) {
            float av = ag[u];
            y0  = fmaf(av, sWL0[u * 64 + 2 * lane],     y0);
            y1v = fmaf(av, sWL0[u * 64 + 2 * lane + 1], y1v);
        }
        o[2 * lane]     = y0;
        o[2 * lane + 1] = y1v;
    }
    {   // y1[w',k] = sum_{u<64} a1a[u,k] WL1a[u,w'] + sum_{u<16} a1b[u,k] WL1b[u,w']
        float y[3] = {0.f, 0.f, 0.f};
#pragma unroll
        for (int u = 0; u < 64; u++) {
            float lw = sWL1a[u * 32 + lane];
#pragma unroll
            for (int k = 0; k < 3; k++) y[k] = fmaf(ag[32 + 3 * u + k], lw, y[k]);
        }
#pragma unroll
        for (int u = 0; u < 16; u++) {
            float lw = sWL1b[u * 32 + lane];
#pragma unroll
            for (int k = 0; k < 3; k++) y[k] = fmaf(ag[224 + 3 * u + k], lw, y[k]);
        }
#pragma unroll
        for (int k = 0; k < 3; k++) o[64 + 3 * lane + k] = y[k];
    }
    if (lane < 16) {   // y2[w',a] = sum_u a2[u,a] WL2[u,w']
        float y[5] = {0.f, 0.f, 0.f, 0.f, 0.f};
#pragma unroll
        for (int u = 0; u < 32; u++) {
            float lw = sWL2[u * 16 + lane];
#pragma unroll
            for (int a = 0; a < 5; a++) y[a] = fmaf(ag[272 + 5 * u + a], lw, y[a]);
        }
#pragma unroll
        for (int a = 0; a < 5; a++) o[160 + 5 * lane + a] = y[a];
    }
}

// ============================================================================
extern "C" void kernel_launch(void* const* d_in, const int* in_sizes, int n_in,
                              void* d_out, int out_size) {
    const float* feats  = (const float*)d_in[0];  // (4,4096,240)
    const float* coords = (const float*)d_in[1];  // (4,4096,3)
    const float* W1 = (const float*)d_in[2];      // (64,32)
    const float* W2 = (const float*)d_in[3];      // (32,64)
    const float* W3 = (const float*)d_in[4];      // (32,16)
    const float* W4 = (const float*)d_in[5];      // (16,32)
    const float* L0 = (const float*)d_in[6];      // (64,64)
    const float* L1 = (const float*)d_in[7];      // (32,32)
    const float* L2 = (const float*)d_in[8];      // (16,16)
    float* out = (float*)d_out;

    fuse_kernel<<<20, 256>>>(W1, W2, W3, W4, L0, L1, L2);
    knn_part_kernel<<<dim3(NNODES / 128, NB, NCHUNK), 128>>>(coords);
    knn_merge_kernel<<<BN / 8, 256>>>();
    agg_kernel<<<BN / 8, 256>>>(feats, coords, out);
}

// round 8
// speedup vs baseline: 1.2419x; 1.2419x over previous
#include <cuda_runtime.h>
#include <cstddef>

#define NNODES 4096
#define NB 4
#define BN (NNODES * NB)
#define DFEAT 240
#define KNN 8
#define NCHUNK 4
#define CHUNK (NNODES / NCHUNK)   // 1024 candidates per chunk

// Scratch (allocation-free rule: __device__ globals)
__device__ int   g_knn[BN * KNN];
__device__ float g_pd[BN * NCHUNK * KNN];
__device__ int   g_pi[BN * NCHUNK * KNN];
// Fused (W @ L) matrices, output scales baked in
__device__ float g_WL0[32 * 64];   // (W2@L0)  * c2/8
__device__ float g_WL1a[64 * 32];  // (W1@L1)  * c1/sqrt(32)
__device__ float g_WL1b[16 * 32];  // (W4@L1)  * c4/sqrt(32)
__device__ float g_WL2[32 * 16];   // (W3@L2)  * c3/4

// T[a][k] = (Cm[a] . ev)[k], Cm = real Wigner 1x1->2 coupling / sqrt(5)
__device__ __forceinline__ void compute_T(float ex, float ey, float ez, float T[5][3]) {
    const float sc = 0.31622776601683794f;   // 1/sqrt(2)/sqrt(5)
    const float tc = 0.18257418583505536f;   // 1/sqrt(6)/sqrt(5)
    T[0][0] = sc * ey;  T[0][1] = sc * ex;   T[0][2] = 0.f;
    T[1][0] = sc * ez;  T[1][1] = 0.f;       T[1][2] = sc * ex;
    T[2][0] = 0.f;      T[2][1] = sc * ez;   T[2][2] = sc * ey;
    T[3][0] = sc * ex;  T[3][1] = -sc * ey;  T[3][2] = 0.f;
    T[4][0] = -tc * ex; T[4][1] = -tc * ey;  T[4][2] = 2.f * tc * ez;
}

// Branchless sorted insert (ascending; bd[7] = worst). Compare-exchange sweep.
// Ties: strict < keeps earlier-inserted (smaller index) ahead.
__device__ __forceinline__ void bubble_insert(float bd[8], int bi[8], float s, int gj) {
    float cur = s; int curi = gj;
#pragma unroll
    for (int p = 0; p < 8; p++) {
        bool pred = cur < bd[p];
        float lo = fminf(bd[p], cur);
        float hi = fmaxf(bd[p], cur);
        bd[p] = lo; cur = hi;
        int ti = bi[p];
        bi[p] = pred ? curi : bi[p];
        curi  = pred ? ti   : curi;
    }
}

// ============================================================================
// Kernel 1a: partial kNN. Thread = (query, chunk). Scans 1024 candidates from
// a float4 (x,y,z,|c|^2/2) shared tile; rank by s = h - q.c (monotone in d^2).
// Per-candidate rare branch -> branchless bubble insert. 2048 warps resident
// (3.46/SMSP) to hide LDS/branch latency.
// ============================================================================
__global__ __launch_bounds__(256) void knn_part_kernel(const float* __restrict__ coords) {
    __shared__ float4 tile[CHUNK];                // 16KB
    int b = blockIdx.y, chunk = blockIdx.z;
    int cbase = chunk * CHUNK;
    const float* cb = coords + (size_t)b * NNODES * 3;

    for (int k = threadIdx.x; k < CHUNK; k += 256) {
        float x = cb[(cbase + k) * 3];
        float y = cb[(cbase + k) * 3 + 1];
        float z = cb[(cbase + k) * 3 + 2];
        tile[k] = make_float4(x, y, z, 0.5f * fmaf(x, x, fmaf(y, y, z * z)));
    }
    __syncthreads();

    int q = (blockIdx.x << 8) + threadIdx.x;
    float qx = cb[3 * q], qy = cb[3 * q + 1], qz = cb[3 * q + 2];
    float nqx = -qx, nqy = -qy, nqz = -qz;

    float bd[8];
    int   bi[8];
#pragma unroll
    for (int p = 0; p < 8; p++) { bd[p] = 3.9e38f; bi[p] = 0x7fffffff; }

#pragma unroll 2
    for (int g = 0; g < CHUNK; g += 4) {
        float4 c0 = tile[g],     c1 = tile[g + 1];
        float4 c2 = tile[g + 2], c3 = tile[g + 3];
        float s0 = fmaf(nqx, c0.x, fmaf(nqy, c0.y, fmaf(nqz, c0.z, c0.w)));
        float s1 = fmaf(nqx, c1.x, fmaf(nqy, c1.y, fmaf(nqz, c1.z, c1.w)));
        float s2 = fmaf(nqx, c2.x, fmaf(nqy, c2.y, fmaf(nqz, c2.z, c2.w)));
        float s3 = fmaf(nqx, c3.x, fmaf(nqy, c3.y, fmaf(nqz, c3.z, c3.w)));
        int j0 = cbase + g;
        if (s0 < bd[7] && j0     != q) bubble_insert(bd, bi, s0, j0);
        if (s1 < bd[7] && j0 + 1 != q) bubble_insert(bd, bi, s1, j0 + 1);
        if (s2 < bd[7] && j0 + 2 != q) bubble_insert(bd, bi, s2, j0 + 2);
        if (s3 < bd[7] && j0 + 3 != q) bubble_insert(bd, bi, s3, j0 + 3);
    }

    int qflat = b * NNODES + q;
    int obase = (qflat * NCHUNK + chunk) * KNN;
#pragma unroll
    for (int r = 0; r < KNN; r++) {
        g_pd[obase + r] = bd[r];
        g_pi[obase + r] = b * NNODES + bi[r];     // flat sender id
    }
}

// ============================================================================
// Kernel 1b: merge. Warp per query: 32 partials (4 chunks x 8) = one per lane,
// 8 rounds of lexicographic (val, idx) butterfly argmin; winner masked by id.
// ============================================================================
__global__ __launch_bounds__(256) void knn_merge_kernel() {
    int warp = threadIdx.x >> 5, lane = threadIdx.x & 31;
    int qf = blockIdx.x * 8 + warp;
    int base = qf * NCHUNK * KNN;                 // 32 contiguous entries

    float v = g_pd[base + lane];
    int  id = g_pi[base + lane];

#pragma unroll
    for (int r = 0; r < KNN; r++) {
        float mv = v; int mi = id;
#pragma unroll
        for (int off = 16; off >= 1; off >>= 1) {
            float ov = __shfl_xor_sync(0xffffffffu, mv, off);
            int   oi = __shfl_xor_sync(0xffffffffu, mi, off);
            if (ov < mv || (ov == mv && oi < mi)) { mv = ov; mi = oi; }
        }
        if (lane == r) g_knn[qf * KNN + r] = mi;  // spread stores
        if (id == mi) v = 3.95e38f;               // node ids unique across chunks
    }
}

// ============================================================================
// Kernel 2: fuse W and L matrices (W commutes with aggregation) + bake scales.
// ============================================================================
__global__ __launch_bounds__(256) void fuse_kernel(
    const float* __restrict__ W1, const float* __restrict__ W2,
    const float* __restrict__ W3, const float* __restrict__ W4,
    const float* __restrict__ L0, const float* __restrict__ L1,
    const float* __restrict__ L2) {
    const float c1 = 0.11180339887498949f;   // sqrt(1/80)
    const float c2 = 0.10206207261596575f;   // sqrt(1/96)
    const float c3 = 0.39528470752104744f;   // sqrt(5/32)
    const float c4 = 0.19364916731037085f;   // sqrt(3/80)
    const float is32 = 0.17677669529663687f; // 1/sqrt(32)
    int idx = blockIdx.x * 256 + threadIdx.x;
    if (idx < 2048) {                         // WL0 = W2@L0 : (32,64)
        int u = idx >> 6, w2 = idx & 63;
        float acc = 0.f;
        for (int w = 0; w < 64; w++) acc = fmaf(W2[u * 64 + w], L0[w * 64 + w2], acc);
        g_WL0[idx] = (c2 * 0.125f) * acc;
    } else if (idx < 4096) {                  // WL1a = W1@L1 : (64,32)
        int t = idx - 2048, u = t >> 5, w2 = t & 31;
        float acc = 0.f;
        for (int w = 0; w < 32; w++) acc = fmaf(W1[u * 32 + w], L1[w * 32 + w2], acc);
        g_WL1a[t] = (c1 * is32) * acc;
    } else if (idx < 4608) {                  // WL1b = W4@L1 : (16,32)
        int t = idx - 4096, u = t >> 5, w2 = t & 31;
        float acc = 0.f;
        for (int w = 0; w < 32; w++) acc = fmaf(W4[u * 32 + w], L1[w * 32 + w2], acc);
        g_WL1b[t] = (c4 * is32) * acc;
    } else {                                  // WL2 = W3@L2 : (32,16)
        int t = idx - 4608, u = t >> 4, w2 = t & 15;
        float acc = 0.f;
        for (int w = 0; w < 16; w++) acc = fmaf(W3[u * 16 + w], L2[w * 16 + w2], acc);
        g_WL2[t] = (c3 * 0.25f) * acc;
    }
}

// ============================================================================
// Kernel 3: fused aggregation. Warp per node. Direct LDG of exactly the
// feature elements each lane needs; neighbor ids + coords front-batched.
// Then fused WL linears from shared.
// ============================================================================
__global__ __launch_bounds__(256) void agg_kernel(
    const float* __restrict__ feats, const float* __restrict__ coords,
    float* __restrict__ out) {
    __shared__ float sWL0[2048], sWL1a[2048], sWL1b[512], sWL2[512];
    __shared__ float sag[8][440];
    for (int k = threadIdx.x; k < 2048; k += 256) { sWL0[k] = g_WL0[k]; sWL1a[k] = g_WL1a[k]; }
    for (int k = threadIdx.x; k < 512;  k += 256) { sWL1b[k] = g_WL1b[k]; sWL2[k] = g_WL2[k]; }

    int warp = threadIdx.x >> 5, lane = threadIdx.x & 31;
    int node = (blockIdx.x << 3) + warp;
    float qx = coords[node * 3], qy = coords[node * 3 + 1], qz = coords[node * 3 + 2];

    // front-batch neighbor ids (32B aligned) and edge vectors
    int4 n0 = *(const int4*)(g_knn + node * KNN);
    int4 n1 = *(const int4*)(g_knn + node * KNN + 4);
    int nbr[8] = {n0.x, n0.y, n0.z, n0.w, n1.x, n1.y, n1.z, n1.w};
    float ex[8], ey[8], ez[8];
#pragma unroll
    for (int r = 0; r < 8; r++) {
        ex[r] = coords[nbr[r] * 3]     - qx;
        ey[r] = coords[nbr[r] * 3 + 1] - qy;
        ez[r] = coords[nbr[r] * 3 + 2] - qz;
    }

    float a0 = 0.f;
    float a1a0[3] = {0.f, 0.f, 0.f};
    float a1a1[3] = {0.f, 0.f, 0.f};
    float a1b[3]  = {0.f, 0.f, 0.f};
    float a2[5]   = {0.f, 0.f, 0.f, 0.f, 0.f};

#pragma unroll
    for (int r = 0; r < KNN; r++) {
        const float* f = feats + (size_t)nbr[r] * DFEAT;
        float f0a = f[lane];                       // coalesced
        float f0b = f[32 + lane];                  // coalesced
        float x1v[3];
#pragma unroll
        for (int i = 0; i < 3; i++) x1v[i] = f[64 + 3 * lane + i];
        float x2v[5];
        if (lane < 16) {
#pragma unroll
            for (int a = 0; a < 5; a++) x2v[a] = f[160 + 5 * lane + a];
        }

        float T[5][3];
        compute_T(ex[r], ey[r], ez[r], T);
        float e[3] = {ex[r], ey[r], ez[r]};

#pragma unroll
        for (int k = 0; k < 3; k++) {
            a1a0[k] = fmaf(f0a, e[k], a1a0[k]);
            a1a1[k] = fmaf(f0b, e[k], a1a1[k]);
        }
#pragma unroll
        for (int i = 0; i < 3; i++) a0 = fmaf(x1v[i], e[i], a0);
#pragma unroll
        for (int a = 0; a < 5; a++)
#pragma unroll
            for (int i = 0; i < 3; i++) a2[a] = fmaf(x1v[i], T[a][i], a2[a]);
        if (lane < 16) {
#pragma unroll
            for (int a = 0; a < 5; a++)
#pragma unroll
                for (int k = 0; k < 3; k++) a1b[k] = fmaf(x2v[a], T[a][k], a1b[k]);
        }
    }

    __syncthreads();   // sWL ready

    // stage aggregates: [0,32) a0 | 32+3u+k (u<64) a1a | 224+3u+k (u<16) a1b | 272+5u+a a2
    float* ag = sag[warp];
    ag[lane] = a0;
#pragma unroll
    for (int k = 0; k < 3; k++) {
        ag[32 + 3 * lane + k]        = a1a0[k];
        ag[32 + 3 * (lane + 32) + k] = a1a1[k];
    }
    if (lane < 16) {
#pragma unroll
        for (int k = 0; k < 3; k++) ag[224 + 3 * lane + k] = a1b[k];
    }
#pragma unroll
    for (int a = 0; a < 5; a++) ag[272 + 5 * lane + a] = a2[a];
    __syncwarp();

    float* o = out + (size_t)node * DFEAT;
    {   // y0[w'] = sum_u a0[u] WL0[u,w']   (w' = 2lane, 2lane+1)
        float y0 = 0.f, y1v = 0.f;
#pragma unroll
        for (int u = 0; u < 32; u++) {
            float av = ag[u];
            y0  = fmaf(av, sWL0[u * 64 + 2 * lane],     y0);
            y1v = fmaf(av, sWL0[u * 64 + 2 * lane + 1], y1v);
        }
        o[2 * lane]     = y0;
        o[2 * lane + 1] = y1v;
    }
    {   // y1[w',k] = sum_{u<64} a1a[u,k] WL1a[u,w'] + sum_{u<16} a1b[u,k] WL1b[u,w']
        float y[3] = {0.f, 0.f, 0.f};
#pragma unroll
        for (int u = 0; u < 64; u++) {
            float lw = sWL1a[u * 32 + lane];
#pragma unroll
            for (int k = 0; k < 3; k++) y[k] = fmaf(ag[32 + 3 * u + k], lw, y[k]);
        }
#pragma unroll
        for (int u = 0; u < 16; u++) {
            float lw = sWL1b[u * 32 + lane];
#pragma unroll
            for (int k = 0; k < 3; k++) y[k] = fmaf(ag[224 + 3 * u + k], lw, y[k]);
        }
#pragma unroll
        for (int k = 0; k < 3; k++) o[64 + 3 * lane + k] = y[k];
    }
    if (lane < 16) {   // y2[w',a] = sum_u a2[u,a] WL2[u,w']
        float y[5] = {0.f, 0.f, 0.f, 0.f, 0.f};
#pragma unroll
        for (int u = 0; u < 32; u++) {
            float lw = sWL2[u * 16 + lane];
#pragma unroll
            for (int a = 0; a < 5; a++) y[a] = fmaf(ag[272 + 5 * u + a], lw, y[a]);
        }
#pragma unroll
        for (int a = 0; a < 5; a++) o[160 + 5 * lane + a] = y[a];
    }
}

// ============================================================================
extern "C" void kernel_launch(void* const* d_in, const int* in_sizes, int n_in,
                              void* d_out, int out_size) {
    const float* feats  = (const float*)d_in[0];  // (4,4096,240)
    const float* coords = (const float*)d_in[1];  // (4,4096,3)
    const float* W1 = (const float*)d_in[2];      // (64,32)
    const float* W2 = (const float*)d_in[3];      // (32,64)
    const float* W3 = (const float*)d_in[4];      // (32,16)
    const float* W4 = (const float*)d_in[5];      // (16,32)
    const float* L0 = (const float*)d_in[6];      // (64,64)
    const float* L1 = (const float*)d_in[7];      // (32,32)
    const float* L2 = (const float*)d_in[8];      // (16,16)
    float* out = (float*)d_out;

    fuse_kernel<<<20, 256>>>(W1, W2, W3, W4, L0, L1, L2);
    knn_part_kernel<<<dim3(NNODES / 256, NB, NCHUNK), 256>>>(coords);
    knn_merge_kernel<<<BN / 8, 256>>>();
    agg_kernel<<<BN / 8, 256>>>(feats, coords, out);
}

// round 9
// speedup vs baseline: 1.7925x; 1.4433x over previous
#include <cuda_runtime.h>
#include <cstddef>
#include <math_constants.h>

#define NNODES 4096
#define NB 4
#define BN (NNODES * NB)
#define DFEAT 240
#define FXSTRIDE 256
#define KNN 8
#define KTHREADS 512
#define KWARPS (KTHREADS / 32)

// Scratch (allocation-free rule: __device__ globals)
__device__ int    g_knn[BN * KNN];
__device__ float4 g_c4[BN];                       // (x,y,z,|c|^2/2)
__device__ float  g_fx[(size_t)BN * FXSTRIDE];    // repacked features
// Fused (W @ L) matrices, output scales baked in
__device__ float g_WL0[32 * 64];   // (W2@L0)  * c2/8
__device__ float g_WL1a[64 * 32];  // (W1@L1)  * c1/sqrt(32)
__device__ float g_WL1b[16 * 32];  // (W4@L1)  * c4/sqrt(32)
__device__ float g_WL2[32 * 16];   // (W3@L2)  * c3/4

// T[a][k] = (Cm[a] . ev)[k], Cm = real Wigner 1x1->2 coupling / sqrt(5)
__device__ __forceinline__ void compute_T(float ex, float ey, float ez, float T[5][3]) {
    const float sc = 0.31622776601683794f;   // 1/sqrt(2)/sqrt(5)
    const float tc = 0.18257418583505536f;   // 1/sqrt(6)/sqrt(5)
    T[0][0] = sc * ey;  T[0][1] = sc * ex;   T[0][2] = 0.f;
    T[1][0] = sc * ez;  T[1][1] = 0.f;       T[1][2] = sc * ex;
    T[2][0] = 0.f;      T[2][1] = sc * ez;   T[2][2] = sc * ey;
    T[3][0] = sc * ex;  T[3][1] = -sc * ey;  T[3][2] = 0.f;
    T[4][0] = -tc * ex; T[4][1] = -tc * ey;  T[4][2] = 2.f * tc * ez;
}

// ============================================================================
// Kernel 0a: coords -> float4 (x,y,z,|c|^2/2)
// ============================================================================
__global__ __launch_bounds__(256) void prep_kernel(const float* __restrict__ coords) {
    int i = blockIdx.x * 256 + threadIdx.x;
    float x = coords[3 * i], y = coords[3 * i + 1], z = coords[3 * i + 2];
    g_c4[i] = make_float4(x, y, z, 0.5f * fmaf(x, x, fmaf(y, y, z * z)));
}

// ============================================================================
// Kernel 0b: repack features per node (warp per node):
//   [0:64)  x0 (as-is)
//   [64 + i*32 + u)  x1[u][i]   (i<3, u<32)
//   [160 + a*16 + u) x2[u][a]   (a<5, u<16)
// Strided reads paid once per node; agg's 8x gathers become coalesced.
// ============================================================================
__global__ __launch_bounds__(256) void repack_kernel(const float* __restrict__ feats) {
    int warp = threadIdx.x >> 5, lane = threadIdx.x & 31;
    int node = blockIdx.x * 8 + warp;
    const float* f = feats + (size_t)node * DFEAT;
    float* o = g_fx + (size_t)node * FXSTRIDE;
    o[lane]      = f[lane];
    o[32 + lane] = f[32 + lane];
    float a = f[64 + 3 * lane], b = f[64 + 3 * lane + 1], c = f[64 + 3 * lane + 2];
    o[64 + lane]  = a;
    o[96 + lane]  = b;
    o[128 + lane] = c;
    int o1 = lane, o2 = lane + 32;                   // x2 flat index a*16+u
    o[160 + o1] = f[160 + 5 * (o1 & 15) + (o1 >> 4)];
    o[160 + o2] = f[160 + 5 * (o2 & 15) + (o2 >> 4)];
    if (lane < 16) o[224 + lane] = f[160 + 5 * lane + 4];
}

// ============================================================================
// Kernel 1: kNN, WARP per query. Top-8 distributed across lanes 0..7 (sorted
// ascending; lane 7 = worst). Per step: 64 candidates (2/lane) from shared
// tile, one warp-uniform vote; inserts are warp-uniform shfl-shift ops.
// Exact, tie = earliest index (ballot processed low->high = index order;
// strict > in the shift ballot keeps earlier-inserted equal values ahead).
// ============================================================================
__global__ __launch_bounds__(KTHREADS) void knn_kernel() {
    __shared__ float4 tile[2048];                 // 32KB (chunked: 2 x 2048)
    const unsigned FULL = 0xffffffffu;
    int b = blockIdx.y;
    int warp = threadIdx.x >> 5, lane = threadIdx.x & 31;
    int q = blockIdx.x * KWARPS + warp;           // query within batch
    int qflat = b * NNODES + q;

    float4 qc = g_c4[qflat];
    float nqx = -qc.x, nqy = -qc.y, nqz = -qc.z;

    float v  = CUDART_INF_F;                      // lane's slot of the top-8 (lanes 0..7)
    int  vid = 0x7fffffff;
    float worst = CUDART_INF_F;

    for (int ch = 0; ch < 2; ch++) {
        int cbase = ch << 11;
        __syncthreads();
        for (int k = threadIdx.x; k < 2048; k += KTHREADS)
            tile[k] = g_c4[b * NNODES + cbase + k];
        __syncthreads();

        for (int s = 0; s < 2048; s += 64) {
            int j0 = s + lane, j1 = s + 32 + lane;
            float4 c0 = tile[j0], c1 = tile[j1];
            float d0 = fmaf(nqx, c0.x, fmaf(nqy, c0.y, fmaf(nqz, c0.z, c0.w)));
            float d1 = fmaf(nqx, c1.x, fmaf(nqy, c1.y, fmaf(nqz, c1.z, c1.w)));
            d0 = (cbase + j0 == q) ? CUDART_INF_F : d0;   // self-exclusion
            d1 = (cbase + j1 == q) ? CUDART_INF_F : d1;

            if (__any_sync(FULL, fminf(d0, d1) < worst)) {
#pragma unroll
                for (int round = 0; round < 2; round++) {
                    float dr = (round == 0) ? d0 : d1;
                    int jbase = cbase + s + (round << 5);
                    unsigned m = __ballot_sync(FULL, dr < worst);
                    while (m) {
                        int src = __ffs(m) - 1; m &= m - 1;
                        float nb = __shfl_sync(FULL, dr, src);
                        if (nb < worst) {                 // warp-uniform
                            int ib = jbase + src;
                            unsigned gt = __ballot_sync(FULL, (lane < 8) && (v > nb));
                            int p = __ffs(gt) - 1;        // nonzero: lane7 has v=worst>nb
                            float vup = __shfl_up_sync(FULL, v, 1);
                            int  iup  = __shfl_up_sync(FULL, vid, 1);
                            if (lane == p)               { v = nb;  vid = ib;  }
                            else if (lane > p && lane < 8) { v = vup; vid = iup; }
                            worst = __shfl_sync(FULL, v, 7);
                        }
                    }
                }
            }
        }
    }

    if (lane < 8) g_knn[qflat * KNN + lane] = b * NNODES + vid;
}

// ============================================================================
// Kernel 2: fuse W and L matrices (W commutes with aggregation) + bake scales.
// ============================================================================
__global__ __launch_bounds__(256) void fuse_kernel(
    const float* __restrict__ W1, const float* __restrict__ W2,
    const float* __restrict__ W3, const float* __restrict__ W4,
    const float* __restrict__ L0, const float* __restrict__ L1,
    const float* __restrict__ L2) {
    const float c1 = 0.11180339887498949f;   // sqrt(1/80)
    const float c2 = 0.10206207261596575f;   // sqrt(1/96)
    const float c3 = 0.39528470752104744f;   // sqrt(5/32)
    const float c4 = 0.19364916731037085f;   // sqrt(3/80)
    const float is32 = 0.17677669529663687f; // 1/sqrt(32)
    int idx = blockIdx.x * 256 + threadIdx.x;
    if (idx < 2048) {                         // WL0 = W2@L0 : (32,64)
        int u = idx >> 6, w2 = idx & 63;
        float acc = 0.f;
        for (int w = 0; w < 64; w++) acc = fmaf(W2[u * 64 + w], L0[w * 64 + w2], acc);
        g_WL0[idx] = (c2 * 0.125f) * acc;
    } else if (idx < 4096) {                  // WL1a = W1@L1 : (64,32)
        int t = idx - 2048, u = t >> 5, w2 = t & 31;
        float acc = 0.f;
        for (int w = 0; w < 32; w++) acc = fmaf(W1[u * 32 + w], L1[w * 32 + w2], acc);
        g_WL1a[t] = (c1 * is32) * acc;
    } else if (idx < 4608) {                  // WL1b = W4@L1 : (16,32)
        int t = idx - 4096, u = t >> 5, w2 = t & 31;
        float acc = 0.f;
        for (int w = 0; w < 32; w++) acc = fmaf(W4[u * 32 + w], L1[w * 32 + w2], acc);
        g_WL1b[t] = (c4 * is32) * acc;
    } else {                                  // WL2 = W3@L2 : (32,16)
        int t = idx - 4608, u = t >> 4, w2 = t & 15;
        float acc = 0.f;
        for (int w = 0; w < 16; w++) acc = fmaf(W3[u * 16 + w], L2[w * 16 + w2], acc);
        g_WL2[t] = (c3 * 0.25f) * acc;
    }
}

// ============================================================================
// Kernel 3: fused aggregation. Warp per node. Coalesced gathers from the
// repacked g_fx layout; neighbor ids + coords front-batched. Fused WL linears.
// ============================================================================
__global__ __launch_bounds__(256) void agg_kernel(float* __restrict__ out) {
    __shared__ float sWL0[2048], sWL1a[2048], sWL1b[512], sWL2[512];
    __shared__ float sag[8][440];
    for (int k = threadIdx.x; k < 2048; k += 256) { sWL0[k] = g_WL0[k]; sWL1a[k] = g_WL1a[k]; }
    for (int k = threadIdx.x; k < 512;  k += 256) { sWL1b[k] = g_WL1b[k]; sWL2[k] = g_WL2[k]; }

    int warp = threadIdx.x >> 5, lane = threadIdx.x & 31;
    int node = (blockIdx.x << 3) + warp;
    float4 qc = g_c4[node];

    // front-batch neighbor ids (32B aligned) and edge vectors
    int4 n0 = *(const int4*)(g_knn + node * KNN);
    int4 n1 = *(const int4*)(g_knn + node * KNN + 4);
    int nbr[8] = {n0.x, n0.y, n0.z, n0.w, n1.x, n1.y, n1.z, n1.w};
    float ex[8], ey[8], ez[8];
#pragma unroll
    for (int r = 0; r < 8; r++) {
        float4 cn = g_c4[nbr[r]];
        ex[r] = cn.x - qc.x;
        ey[r] = cn.y - qc.y;
        ez[r] = cn.z - qc.z;
    }

    float a0 = 0.f;
    float a1a0[3] = {0.f, 0.f, 0.f};
    float a1a1[3] = {0.f, 0.f, 0.f};
    float a1b[3]  = {0.f, 0.f, 0.f};
    float a2[5]   = {0.f, 0.f, 0.f, 0.f, 0.f};

#pragma unroll
    for (int r = 0; r < KNN; r++) {
        const float* f = g_fx + (size_t)nbr[r] * FXSTRIDE;
        float f0a = f[lane];                       // coalesced
        float f0b = f[32 + lane];                  // coalesced
        float x1v[3];
#pragma unroll
        for (int i = 0; i < 3; i++) x1v[i] = f[64 + i * 32 + lane];   // coalesced
        float x2v[5];
        if (lane < 16) {
#pragma unroll
            for (int a = 0; a < 5; a++) x2v[a] = f[160 + a * 16 + lane];  // coalesced
        }

        float T[5][3];
        compute_T(ex[r], ey[r], ez[r], T);
        float e[3] = {ex[r], ey[r], ez[r]};

#pragma unroll
        for (int k = 0; k < 3; k++) {
            a1a0[k] = fmaf(f0a, e[k], a1a0[k]);
            a1a1[k] = fmaf(f0b, e[k], a1a1[k]);
        }
#pragma unroll
        for (int i = 0; i < 3; i++) a0 = fmaf(x1v[i], e[i], a0);
#pragma unroll
        for (int a = 0; a < 5; a++)
#pragma unroll
            for (int i = 0; i < 3; i++) a2[a] = fmaf(x1v[i], T[a][i], a2[a]);
        if (lane < 16) {
#pragma unroll
            for (int a = 0; a < 5; a++)
#pragma unroll
                for (int k = 0; k < 3; k++) a1b[k] = fmaf(x2v[a], T[a][k], a1b[k]);
        }
    }

    __syncthreads();   // sWL ready

    // stage aggregates: [0,32) a0 | 32+3u+k (u<64) a1a | 224+3u+k (u<16) a1b | 272+5u+a a2
    float* ag = sag[warp];
    ag[lane] = a0;
#pragma unroll
    for (int k = 0; k < 3; k++) {
        ag[32 + 3 * lane + k]        = a1a0[k];
        ag[32 + 3 * (lane + 32) + k] = a1a1[k];
    }
    if (lane < 16) {
#pragma unroll
        for (int k = 0; k < 3; k++) ag[224 + 3 * lane + k] = a1b[k];
    }
#pragma unroll
    for (int a = 0; a < 5; a++) ag[272 + 5 * lane + a] = a2[a];
    __syncwarp();

    float* o = out + (size_t)node * DFEAT;
    {   // y0[w'] = sum_u a0[u] WL0[u,w']   (w' = 2lane, 2lane+1)
        float y0 = 0.f, y1v = 0.f;
#pragma unroll
        for (int u = 0; u < 32; u++) {
            float av = ag[u];
            y0  = fmaf(av, sWL0[u * 64 + 2 * lane],     y0);
            y1v = fmaf(av, sWL0[u * 64 + 2 * lane + 1], y1v);
        }
        o[2 * lane]     = y0;
        o[2 * lane + 1] = y1v;
    }
    {   // y1[w',k] = sum_{u<64} a1a[u,k] WL1a[u,w'] + sum_{u<16} a1b[u,k] WL1b[u,w']
        float y[3] = {0.f, 0.f, 0.f};
#pragma unroll
        for (int u = 0; u < 64; u++) {
            float lw = sWL1a[u * 32 + lane];
#pragma unroll
            for (int k = 0; k < 3; k++) y[k] = fmaf(ag[32 + 3 * u + k], lw, y[k]);
        }
#pragma unroll
        for (int u = 0; u < 16; u++) {
            float lw = sWL1b[u * 32 + lane];
#pragma unroll
            for (int k = 0; k < 3; k++) y[k] = fmaf(ag[224 + 3 * u + k], lw, y[k]);
        }
#pragma unroll
        for (int k = 0; k < 3; k++) o[64 + 3 * lane + k] = y[k];
    }
    if (lane < 16) {   // y2[w',a] = sum_u a2[u,a] WL2[u,w']
        float y[5] = {0.f, 0.f, 0.f, 0.f, 0.f};
#pragma unroll
        for (int u = 0; u < 32; u++) {
            float lw = sWL2[u * 16 + lane];
#pragma unroll
            for (int a = 0; a < 5; a++) y[a] = fmaf(ag[272 + 5 * u + a], lw, y[a]);
        }
#pragma unroll
        for (int a = 0; a < 5; a++) o[160 + 5 * lane + a] = y[a];
    }
}

// ============================================================================
extern "C" void kernel_launch(void* const* d_in, const int* in_sizes, int n_in,
                              void* d_out, int out_size) {
    const float* feats  = (const float*)d_in[0];  // (4,4096,240)
    const float* coords = (const float*)d_in[1];  // (4,4096,3)
    const float* W1 = (const float*)d_in[2];      // (64,32)
    const float* W2 = (const float*)d_in[3];      // (32,64)
    const float* W3 = (const float*)d_in[4];      // (32,16)
    const float* W4 = (const float*)d_in[5];      // (16,32)
    const float* L0 = (const float*)d_in[6];      // (64,64)
    const float* L1 = (const float*)d_in[7];      // (32,32)
    const float* L2 = (const float*)d_in[8];      // (16,16)
    float* out = (float*)d_out;

    prep_kernel<<<BN / 256, 256>>>(coords);
    repack_kernel<<<BN / 8, 256>>>(feats);
    fuse_kernel<<<20, 256>>>(W1, W2, W3, W4, L0, L1, L2);
    knn_kernel<<<dim3(NNODES / KWARPS, NB), KTHREADS>>>();
    agg_kernel<<<BN / 8, 256>>>(out);
}

// round 10
// speedup vs baseline: 1.8541x; 1.0344x over previous
#include <cuda_runtime.h>
#include <cstddef>
#include <math_constants.h>

#define NNODES 4096
#define NB 4
#define BN (NNODES * NB)
#define DFEAT 240
#define FXSTRIDE 256
#define KNN 8
#define KTHREADS 512
#define KWARPS (KTHREADS / 32)

// Scratch (allocation-free rule: __device__ globals)
__device__ int    g_knn[BN * KNN];
__device__ float4 g_c4[BN];                       // (x,y,z,|c|^2/2)
__device__ float  g_fx[(size_t)BN * FXSTRIDE];    // repacked features
// Fused (W @ L) matrices, output scales baked in
__device__ float g_WL0[32 * 64];   // (W2@L0)  * c2/8
__device__ float g_WL1a[64 * 32];  // (W1@L1)  * c1/sqrt(32)
__device__ float g_WL1b[16 * 32];  // (W4@L1)  * c4/sqrt(32)
__device__ float g_WL2[32 * 16];   // (W3@L2)  * c3/4

// T[a][k] = (Cm[a] . ev)[k], Cm = real Wigner 1x1->2 coupling / sqrt(5)
__device__ __forceinline__ void compute_T(float ex, float ey, float ez, float T[5][3]) {
    const float sc = 0.31622776601683794f;   // 1/sqrt(2)/sqrt(5)
    const float tc = 0.18257418583505536f;   // 1/sqrt(6)/sqrt(5)
    T[0][0] = sc * ey;  T[0][1] = sc * ex;   T[0][2] = 0.f;
    T[1][0] = sc * ez;  T[1][1] = 0.f;       T[1][2] = sc * ex;
    T[2][0] = 0.f;      T[2][1] = sc * ez;   T[2][2] = sc * ey;
    T[3][0] = sc * ex;  T[3][1] = -sc * ey;  T[3][2] = 0.f;
    T[4][0] = -tc * ex; T[4][1] = -tc * ey;  T[4][2] = 2.f * tc * ez;
}

// ============================================================================
// Kernel 0: repack features per node (warp per node) + build g_c4.
// Layout per node (stride 256 floats):
//   [4u .. 4u+4)   = (x0[u], x1[u][0], x1[u][1], x1[u][2])   u<32  (LDG.128)
//   [128 + u)      = x0[32+u]                                 u<32
//   [160 + 4u ..)  = x2[u][0..3]                              u<16  (LDG.128)
//   [224 + u)      = x2[u][4]                                 u<16
// ============================================================================
__global__ __launch_bounds__(256) void repack_kernel(
    const float* __restrict__ feats, const float* __restrict__ coords) {
    int warp = threadIdx.x >> 5, lane = threadIdx.x & 31;
    int node = blockIdx.x * 8 + warp;
    const float* f = feats + (size_t)node * DFEAT;
    float* o = g_fx + (size_t)node * FXSTRIDE;
    float4 A;
    A.x = f[lane];
    A.y = f[64 + 3 * lane];
    A.z = f[64 + 3 * lane + 1];
    A.w = f[64 + 3 * lane + 2];
    *(float4*)(o + 4 * lane) = A;
    o[128 + lane] = f[32 + lane];
    if (lane < 16) {
        float4 X;
        X.x = f[160 + 5 * lane];
        X.y = f[160 + 5 * lane + 1];
        X.z = f[160 + 5 * lane + 2];
        X.w = f[160 + 5 * lane + 3];
        *(float4*)(o + 160 + 4 * lane) = X;
        o[224 + lane] = f[160 + 5 * lane + 4];
    }
    if (threadIdx.x < 8) {                        // g_c4 for this block's 8 nodes
        int n2 = blockIdx.x * 8 + threadIdx.x;
        float x = coords[3 * n2], y = coords[3 * n2 + 1], z = coords[3 * n2 + 2];
        g_c4[n2] = make_float4(x, y, z, 0.5f * fmaf(x, x, fmaf(y, y, z * z)));
    }
}

// ============================================================================
// Kernel 1: kNN, WARP per query, TOP-9 distributed across lanes 0..8 (sorted
// ascending; lane 8 = worst). No per-candidate self-exclusion: the query
// itself has the strict unique minimum score (-|q|^2/2; every other candidate
// differs by |c-q|^2/2 > 0), so it provably ends in lane 0 and lanes 1..8 are
// the true top-8 neighbors. Per step: 128 candidates (4/lane) from shared
// tile, one warp-uniform vote; inserts are warp-uniform shfl-shift ops.
// Tie = earliest index (ballot low->high = index order; strict > keeps
// earlier-inserted equal values ahead) — matches jax.lax.top_k.
// ============================================================================
__global__ __launch_bounds__(KTHREADS) void knn_kernel() {
    __shared__ float4 tile[2048];                 // 32KB (chunked: 2 x 2048)
    const unsigned FULL = 0xffffffffu;
    int b = blockIdx.y;
    int warp = threadIdx.x >> 5, lane = threadIdx.x & 31;
    int q = blockIdx.x * KWARPS + warp;           // query within batch
    int qflat = b * NNODES + q;

    float4 qc = g_c4[qflat];
    float nqx = -qc.x, nqy = -qc.y, nqz = -qc.z;

    float v  = CUDART_INF_F;                      // lane's slot of the top-9 (lanes 0..8)
    int  vid = 0x7fffffff;
    float worst = CUDART_INF_F;                   // = v at lane 8

    for (int ch = 0; ch < 2; ch++) {
        int cbase = ch << 11;
        __syncthreads();
        for (int k = threadIdx.x; k < 2048; k += KTHREADS)
            tile[k] = g_c4[b * NNODES + cbase + k];
        __syncthreads();

        for (int s = 0; s < 2048; s += 128) {
            float d[4];
#pragma unroll
            for (int t = 0; t < 4; t++) {
                float4 c = tile[s + (t << 5) + lane];
                d[t] = fmaf(nqx, c.x, fmaf(nqy, c.y, fmaf(nqz, c.z, c.w)));
            }
            float m = fminf(fminf(d[0], d[1]), fminf(d[2], d[3]));
            if (__any_sync(FULL, m < worst)) {
#pragma unroll
                for (int t = 0; t < 4; t++) {
                    unsigned mask = __ballot_sync(FULL, d[t] < worst);
                    int jbase = cbase + s + (t << 5);
                    while (mask) {
                        int src = __ffs(mask) - 1; mask &= mask - 1;
                        float nb = __shfl_sync(FULL, d[t], src);
                        if (nb < worst) {                 // warp-uniform recheck
                            int ib = jbase + src;
                            unsigned gt = __ballot_sync(FULL, (lane < 9) && (v > nb));
                            int p = __ffs(gt) - 1;        // nonzero: lane8 has v=worst>nb
                            float vup = __shfl_up_sync(FULL, v, 1);
                            int  iup  = __shfl_up_sync(FULL, vid, 1);
                            if (lane == p)                 { v = nb;  vid = ib;  }
                            else if (lane > p && lane < 9) { v = vup; vid = iup; }
                            worst = __shfl_sync(FULL, v, 8);
                        }
                    }
                }
            }
        }
    }

    if (lane >= 1 && lane < 9)                    // lane 0 = self; drop it
        g_knn[qflat * KNN + (lane - 1)] = b * NNODES + vid;
}

// ============================================================================
// Kernel 2: fuse W and L matrices (W commutes with aggregation) + bake scales.
// ============================================================================
__global__ __launch_bounds__(256) void fuse_kernel(
    const float* __restrict__ W1, const float* __restrict__ W2,
    const float* __restrict__ W3, const float* __restrict__ W4,
    const float* __restrict__ L0, const float* __restrict__ L1,
    const float* __restrict__ L2) {
    const float c1 = 0.11180339887498949f;   // sqrt(1/80)
    const float c2 = 0.10206207261596575f;   // sqrt(1/96)
    const float c3 = 0.39528470752104744f;   // sqrt(5/32)
    const float c4 = 0.19364916731037085f;   // sqrt(3/80)
    const float is32 = 0.17677669529663687f; // 1/sqrt(32)
    int idx = blockIdx.x * 256 + threadIdx.x;
    if (idx < 2048) {                         // WL0 = W2@L0 : (32,64)
        int u = idx >> 6, w2 = idx & 63;
        float acc = 0.f;
        for (int w = 0; w < 64; w++) acc = fmaf(W2[u * 64 + w], L0[w * 64 + w2], acc);
        g_WL0[idx] = (c2 * 0.125f) * acc;
    } else if (idx < 4096) {                  // WL1a = W1@L1 : (64,32)
        int t = idx - 2048, u = t >> 5, w2 = t & 31;
        float acc = 0.f;
        for (int w = 0; w < 32; w++) acc = fmaf(W1[u * 32 + w], L1[w * 32 + w2], acc);
        g_WL1a[t] = (c1 * is32) * acc;
    } else if (idx < 4608) {                  // WL1b = W4@L1 : (16,32)
        int t = idx - 4096, u = t >> 5, w2 = t & 31;
        float acc = 0.f;
        for (int w = 0; w < 32; w++) acc = fmaf(W4[u * 32 + w], L1[w * 32 + w2], acc);
        g_WL1b[t] = (c4 * is32) * acc;
    } else {                                  // WL2 = W3@L2 : (32,16)
        int t = idx - 4608, u = t >> 4, w2 = t & 15;
        float acc = 0.f;
        for (int w = 0; w < 16; w++) acc = fmaf(W3[u * 16 + w], L2[w * 16 + w2], acc);
        g_WL2[t] = (c3 * 0.25f) * acc;
    }
}

// ============================================================================
// Kernel 3: fused aggregation. Warp per node. Vectorized coalesced gathers
// from the packed g_fx layout (2 LDG.128 + 2 scalar per edge per lane);
// neighbor ids + coords front-batched. Fused WL linears from shared.
// ============================================================================
__global__ __launch_bounds__(256) void agg_kernel(float* __restrict__ out) {
    __shared__ float sWL0[2048], sWL1a[2048], sWL1b[512], sWL2[512];
    __shared__ float sag[8][440];
    for (int k = threadIdx.x; k < 2048; k += 256) { sWL0[k] = g_WL0[k]; sWL1a[k] = g_WL1a[k]; }
    for (int k = threadIdx.x; k < 512;  k += 256) { sWL1b[k] = g_WL1b[k]; sWL2[k] = g_WL2[k]; }

    int warp = threadIdx.x >> 5, lane = threadIdx.x & 31;
    int node = (blockIdx.x << 3) + warp;
    float4 qc = g_c4[node];

    // front-batch neighbor ids (32B aligned) and edge vectors
    int4 n0 = *(const int4*)(g_knn + node * KNN);
    int4 n1 = *(const int4*)(g_knn + node * KNN + 4);
    int nbr[8] = {n0.x, n0.y, n0.z, n0.w, n1.x, n1.y, n1.z, n1.w};
    float ex[8], ey[8], ez[8];
#pragma unroll
    for (int r = 0; r < 8; r++) {
        float4 cn = g_c4[nbr[r]];
        ex[r] = cn.x - qc.x;
        ey[r] = cn.y - qc.y;
        ez[r] = cn.z - qc.z;
    }

    float a0 = 0.f;
    float a1a0[3] = {0.f, 0.f, 0.f};
    float a1a1[3] = {0.f, 0.f, 0.f};
    float a1b[3]  = {0.f, 0.f, 0.f};
    float a2[5]   = {0.f, 0.f, 0.f, 0.f, 0.f};

#pragma unroll
    for (int r = 0; r < KNN; r++) {
        const float* f = g_fx + (size_t)nbr[r] * FXSTRIDE;
        float4 A = *(const float4*)(f + 4 * lane);        // x0a, x1[0..2]
        float f0b = f[128 + lane];                        // x0b
        float4 X = make_float4(0.f, 0.f, 0.f, 0.f);
        float x4 = 0.f;
        if (lane < 16) {
            X  = *(const float4*)(f + 160 + 4 * lane);    // x2[0..3]
            x4 = f[224 + lane];                           // x2[4]
        }

        float T[5][3];
        compute_T(ex[r], ey[r], ez[r], T);
        float e[3] = {ex[r], ey[r], ez[r]};
        float x1v[3] = {A.y, A.z, A.w};
        float x2v[5] = {X.x, X.y, X.z, X.w, x4};

#pragma unroll
        for (int k = 0; k < 3; k++) {
            a1a0[k] = fmaf(A.x, e[k], a1a0[k]);
            a1a1[k] = fmaf(f0b, e[k], a1a1[k]);
        }
#pragma unroll
        for (int i = 0; i < 3; i++) a0 = fmaf(x1v[i], e[i], a0);
#pragma unroll
        for (int a = 0; a < 5; a++)
#pragma unroll
            for (int i = 0; i < 3; i++) a2[a] = fmaf(x1v[i], T[a][i], a2[a]);
        if (lane < 16) {
#pragma unroll
            for (int a = 0; a < 5; a++)
#pragma unroll
                for (int k = 0; k < 3; k++) a1b[k] = fmaf(x2v[a], T[a][k], a1b[k]);
        }
    }

    __syncthreads();   // sWL ready

    // stage aggregates: [0,32) a0 | 32+3u+k (u<64) a1a | 224+3u+k (u<16) a1b | 272+5u+a a2
    float* ag = sag[warp];
    ag[lane] = a0;
#pragma unroll
    for (int k = 0; k < 3; k++) {
        ag[32 + 3 * lane + k]        = a1a0[k];
        ag[32 + 3 * (lane + 32) + k] = a1a1[k];
    }
    if (lane < 16) {
#pragma unroll
        for (int k = 0; k < 3; k++) ag[224 + 3 * lane + k] = a1b[k];
    }
#pragma unroll
    for (int a = 0; a < 5; a++) ag[272 + 5 * lane + a] = a2[a];
    __syncwarp();

    float* o = out + (size_t)node * DFEAT;
    {   // y0[w'] = sum_u a0[u] WL0[u,w']   (w' = 2lane, 2lane+1)
        float y0 = 0.f, y1v = 0.f;
#pragma unroll
        for (int u = 0; u < 32; u++) {
            float av = ag[u];
            y0  = fmaf(av, sWL0[u * 64 + 2 * lane],     y0);
            y1v = fmaf(av, sWL0[u * 64 + 2 * lane + 1], y1v);
        }
        o[2 * lane]     = y0;
        o[2 * lane + 1] = y1v;
    }
    {   // y1[w',k] = sum_{u<64} a1a[u,k] WL1a[u,w'] + sum_{u<16} a1b[u,k] WL1b[u,w']
        float y[3] = {0.f, 0.f, 0.f};
#pragma unroll
        for (int u = 0; u < 64; u++) {
            float lw = sWL1a[u * 32 + lane];
#pragma unroll
            for (int k = 0; k < 3; k++) y[k] = fmaf(ag[32 + 3 * u + k], lw, y[k]);
        }
#pragma unroll
        for (int u = 0; u < 16; u++) {
            float lw = sWL1b[u * 32 + lane];
#pragma unroll
            for (int k = 0; k < 3; k++) y[k] = fmaf(ag[224 + 3 * u + k], lw, y[k]);
        }
#pragma unroll
        for (int k = 0; k < 3; k++) o[64 + 3 * lane + k] = y[k];
    }
    if (lane < 16) {   // y2[w',a] = sum_u a2[u,a] WL2[u,w']
        float y[5] = {0.f, 0.f, 0.f, 0.f, 0.f};
#pragma unroll
        for (int u = 0; u < 32; u++) {
            float lw = sWL2[u * 16 + lane];
#pragma unroll
            for (int a = 0; a < 5; a++) y[a] = fmaf(ag[272 + 5 * u + a], lw, y[a]);
        }
#pragma unroll
        for (int a = 0; a < 5; a++) o[160 + 5 * lane + a] = y[a];
    }
}

// ============================================================================
extern "C" void kernel_launch(void* const* d_in, const int* in_sizes, int n_in,
                              void* d_out, int out_size) {
    const float* feats  = (const float*)d_in[0];  // (4,4096,240)
    const float* coords = (const float*)d_in[1];  // (4,4096,3)
    const float* W1 = (const float*)d_in[2];      // (64,32)
    const float* W2 = (const float*)d_in[3];      // (32,64)
    const float* W3 = (const float*)d_in[4];      // (32,16)
    const float* W4 = (const float*)d_in[5];      // (16,32)
    const float* L0 = (const float*)d_in[6];      // (64,64)
    const float* L1 = (const float*)d_in[7];      // (32,32)
    const float* L2 = (const float*)d_in[8];      // (16,16)
    float* out = (float*)d_out;

    repack_kernel<<<BN / 8, 256>>>(feats, coords);
    fuse_kernel<<<20, 256>>>(W1, W2, W3, W4, L0, L1, L2);
    knn_kernel<<<dim3(NNODES / KWARPS, NB), KTHREADS>>>();
    agg_kernel<<<BN / 8, 256>>>(out);
}